// round 2
// baseline (speedup 1.0000x reference)
#include <cuda_runtime.h>
#include <cstdint>

// LocallyConnected2d, Round 2: f32x2-packed (FFMA2) over the w dimension.
// y[b,o,h,w] = sum_{i,kh,kw} x_pad[b,i,h+kh-1,w+kw-1]*W[i,o,h,w,kh,kw] + bias[o,h,w]
// x[64,64,32,32], W[64,64,32,32,3,3], bias[64,32,32], y[64,64,32,32], all f32.
//
// Grid 256 = 32 h x 4 b-tiles(16) x 2 o-tiles(32); 256 threads.
// Thread tile: 2w x 8o x 4b -> 32 f32x2 accumulators.
// Smem: Ws reordered to [o][kk][w] (w-contiguous -> wv2 is one LDS.64),
//       Xs[kh][b][36] (col-contiguous, halo cols 0/33 stay zero -> xv2 via
//       sliding-window LDS.64 + one pack for the middle tap).

#define THREADS 256
typedef unsigned long long ull;

__device__ __forceinline__ ull ffma2(ull a, ull b, ull c) {
    ull d;
    asm("fma.rn.f32x2 %0, %1, %2, %3;" : "=l"(d) : "l"(a), "l"(b), "l"(c));
    return d;
}
__device__ __forceinline__ ull fadd2(ull a, ull b) {
    ull d;
    asm("add.rn.f32x2 %0, %1, %2;" : "=l"(d) : "l"(a), "l"(b));
    return d;
}
__device__ __forceinline__ ull mid2(ull A, ull B) {  // {A.hi, B.lo}
    float ax, ay, bx, by; ull d;
    asm("mov.b64 {%0,%1}, %2;" : "=f"(ax), "=f"(ay) : "l"(A));
    asm("mov.b64 {%0,%1}, %2;" : "=f"(bx), "=f"(by) : "l"(B));
    asm("mov.b64 %0, {%1,%2};" : "=l"(d) : "f"(ay), "f"(bx));
    return d;
}

__global__ __launch_bounds__(THREADS, 2)
void lc2d_kernel(const float* __restrict__ x,
                 const float* __restrict__ wgt,
                 const float* __restrict__ bias,
                 float* __restrict__ out)
{
    // Ws float layout: [o(32)][kk(9)][w(32)]  (w contiguous)
    __shared__ __align__(16) float Ws[32 * 9 * 32];
    // Xs float layout: [kh(3)][b(16)][cc(36)], cc = col+1, halo/oob stay zero
    __shared__ __align__(16) float Xs[3][16][36];

    const int tid  = threadIdx.x;
    const int bidx = blockIdx.x;
    const int h    = bidx >> 3;
    const int rem  = bidx & 7;
    const int b0   = (rem >> 1) * 16;   // batch tile base
    const int o0   = (rem & 1) * 32;    // cout tile base

    const int wp  = tid & 15;           // w-pair: covers w = 2wp, 2wp+1
    const int og  = (tid >> 4) & 3;     // 8 couts each
    const int bg  = tid >> 6;           // 4 batches each
    const int bl0 = bg * 4;

    // zero Xs once (halo cols + OOB rows persist as zero across all ci)
    for (int q = tid; q < 3 * 16 * 36; q += THREADS)
        ((float*)Xs)[q] = 0.0f;
    __syncthreads();

    ull acc[8][4];
    #pragma unroll
    for (int oi = 0; oi < 8; oi++)
        #pragma unroll
        for (int bi = 0; bi < 4; bi++)
            acc[oi][bi] = 0ull;

    const float* wbase = wgt + (size_t)(0 * 64 + o0) * 9216 + h * 288;

    for (int ci = 0; ci < 64; ci++) {
        // ---- stage weights: 2304 float4-coalesced loads, reorder to [o][kk][w] ----
        {
            const float* wb = wbase + (size_t)ci * 64 * 9216;
            #pragma unroll
            for (int s = 0; s < 9; s++) {
                int q4 = tid + THREADS * s;        // 0..2303
                int o  = q4 / 72;                  // 72 float4 per o-row
                int j  = q4 % 72;
                float4 v = *(const float4*)(wb + (size_t)o * 9216 + 4 * j);
                float vv[4] = {v.x, v.y, v.z, v.w};
                #pragma unroll
                for (int e = 0; e < 4; e++) {
                    int idx = 4 * j + e;           // = w*9 + kk in gmem order
                    int w  = idx / 9;
                    int kk = idx - 9 * w;
                    Ws[o * 288 + kk * 32 + w] = vv[e];
                }
            }
        }
        // ---- stage x: 16b x 3 rows x 32 cols into Xs[hh][b][c+1] ----
        #pragma unroll
        for (int t = 0; t < 6; t++) {
            int q  = tid + THREADS * t;            // 0..1535
            int bb = q / 96;
            int r  = q - 96 * bb;
            int hh = r >> 5;
            int c  = r & 31;
            int row = h - 1 + hh;
            if ((unsigned)row < 32u)
                Xs[hh][bb][c + 1] =
                    x[((size_t)(b0 + bb) * 64 + ci) * 1024 + row * 32 + c];
        }
        __syncthreads();

        // ---- compute ----
        const ull* wsu = (const ull*)Ws;
        #pragma unroll
        for (int kh = 0; kh < 3; kh++) {
            ull A[4], Bv[4];
            #pragma unroll
            for (int bi = 0; bi < 4; bi++) {
                const ull* row = (const ull*)&Xs[kh][bl0 + bi][0];
                A[bi]  = row[wp];       // cols (2wp, 2wp+1)   -> kw=0 tap
                Bv[bi] = row[wp + 1];   // cols (2wp+2, 2wp+3) -> kw=2 tap
            }
            #pragma unroll
            for (int kw = 0; kw < 3; kw++) {
                const int kk = kh * 3 + kw;
                ull p[4];
                #pragma unroll
                for (int bi = 0; bi < 4; bi++)
                    p[bi] = (kw == 0) ? A[bi] : (kw == 2) ? Bv[bi] : mid2(A[bi], Bv[bi]);
                #pragma unroll
                for (int oi = 0; oi < 8; oi++) {
                    ull wv = wsu[(og * 8 + oi) * 144 + kk * 16 + wp];
                    #pragma unroll
                    for (int bi = 0; bi < 4; bi++)
                        acc[oi][bi] = ffma2(p[bi], wv, acc[oi][bi]);
                }
            }
        }
        __syncthreads();
    }

    // ---- epilogue: packed bias add, STG.64 ----
    #pragma unroll
    for (int oi = 0; oi < 8; oi++) {
        const int o = o0 + og * 8 + oi;
        const ull bv = *(const ull*)(bias + o * 1024 + h * 32 + 2 * wp);
        #pragma unroll
        for (int bi = 0; bi < 4; bi++) {
            const int b = b0 + bl0 + bi;
            *(ull*)(out + ((size_t)(b * 64 + o) * 32 + h) * 32 + 2 * wp) =
                fadd2(acc[oi][bi], bv);
        }
    }
}

extern "C" void kernel_launch(void* const* d_in, const int* in_sizes, int n_in,
                              void* d_out, int out_size)
{
    const float* x    = (const float*)d_in[0];
    const float* wgt  = (const float*)d_in[1];
    const float* bias = (const float*)d_in[2];
    float* out        = (float*)d_out;

    lc2d_kernel<<<256, THREADS>>>(x, wgt, bias, out);
}